// round 8
// baseline (speedup 1.0000x reference)
#include <cuda_runtime.h>
#include <cuda_bf16.h>

// Problem constants (fixed by setup_inputs): B=2, L=2048, E=512, window=64
#define L_SEQ   2048
#define E_DIM   512
#define B_BATCH 2
#define M_ROWS  (B_BATCH * L_SEQ)   // 4096

// ---------------- scratch (device globals; no allocation allowed) ----------
__device__ float g_q[M_ROWS * E_DIM];
__device__ float g_k[M_ROWS * E_DIM];
__device__ float g_v[M_ROWS * E_DIM];

typedef unsigned long long u64;

__device__ __forceinline__ u64 pk2(float lo, float hi) {
    u64 r;
    asm("mov.b64 %0, {%1,%2};" : "=l"(r) : "f"(lo), "f"(hi));
    return r;
}
__device__ __forceinline__ void fma2(u64 &d, u64 a, u64 b) {
    asm("fma.rn.f32x2 %0, %1, %2, %0;" : "+l"(d) : "l"(a), "l"(b));
}
__device__ __forceinline__ void unpk2(float &lo, float &hi, u64 v) {
    asm("mov.b64 {%0,%1}, %2;" : "=f"(lo), "=f"(hi) : "l"(v));
}

// ============================================================================
// Kernel 1: QKV projection.  q[m][f] = sum_e X[m][e] * W[f][e] + b[f]
// Tiled SGEMM, BM=BN=64, BK=16, 256 threads, 4x4 microtile, packed FFMA2.
// A operand is stored into SMEM pre-duplicated as (a,a) u64 pairs so the
// inner loop is 3x LDS.128 + 8x FFMA2 per k (FMA-pipe bound).
// grid = (M/64, 24): blockIdx.y selects which of {Wq,Wk,Wv} and the 64-col tile.
// ============================================================================
#define BM 64
#define BN 64
#define BK 16

__global__ void __launch_bounds__(256) qkv_gemm(
    const float* __restrict__ X,
    const float* __restrict__ Wq, const float* __restrict__ Wk, const float* __restrict__ Wv,
    const float* __restrict__ bq, const float* __restrict__ bk, const float* __restrict__ bv)
{
    __shared__ u64   As2[BK][BM + 2];   // pad 2 u64 (16B) -> rows stay 16B aligned
    __shared__ float Bs [BK][BN + 4];   // pad 4 floats (16B)

    const int t  = threadIdx.x;
    const int m0 = blockIdx.x * BM;
    const int nb = blockIdx.y;           // 0..23
    const int mat = nb >> 3;             // 0=q, 1=k, 2=v (512/64 = 8 tiles each)
    const int f0  = (nb & 7) * BN;

    const float* W    = (mat == 0) ? Wq : (mat == 1) ? Wk : Wv;
    const float* bias = (mat == 0) ? bq : (mat == 1) ? bk : bv;
    float*       out  = (mat == 0) ? g_q : (mat == 1) ? g_k : g_v;

    const int lrow = t >> 2;            // 0..63
    const int lc4  = (t & 3) * 4;       // 0,4,8,12
    const float* Aptr = X + (m0 + lrow) * E_DIM + lc4;
    const float* Bptr = W + (f0 + lrow) * E_DIM + lc4;

    const int tx = t & 15;              // output col group
    const int ty = t >> 4;              // output row group

    u64 acc[4][2];
#pragma unroll
    for (int i = 0; i < 4; i++) { acc[i][0] = 0ull; acc[i][1] = 0ull; }

    for (int kt = 0; kt < E_DIM; kt += BK) {
        float4 av = *(const float4*)(Aptr + kt);
        float4 bw = *(const float4*)(Bptr + kt);
        As2[lc4 + 0][lrow] = pk2(av.x, av.x);
        As2[lc4 + 1][lrow] = pk2(av.y, av.y);
        As2[lc4 + 2][lrow] = pk2(av.z, av.z);
        As2[lc4 + 3][lrow] = pk2(av.w, av.w);
        Bs[lc4 + 0][lrow] = bw.x;
        Bs[lc4 + 1][lrow] = bw.y;
        Bs[lc4 + 2][lrow] = bw.z;
        Bs[lc4 + 3][lrow] = bw.w;
        __syncthreads();

#pragma unroll
        for (int k = 0; k < BK; k++) {
            ulonglong2 a01 = *(const ulonglong2*)&As2[k][ty * 4];
            ulonglong2 a23 = *(const ulonglong2*)&As2[k][ty * 4 + 2];
            ulonglong2 bb  = *(const ulonglong2*)&Bs[k][tx * 4];   // 4 floats = 2 pairs
            fma2(acc[0][0], a01.x, bb.x); fma2(acc[0][1], a01.x, bb.y);
            fma2(acc[1][0], a01.y, bb.x); fma2(acc[1][1], a01.y, bb.y);
            fma2(acc[2][0], a23.x, bb.x); fma2(acc[2][1], a23.x, bb.y);
            fma2(acc[3][0], a23.y, bb.x); fma2(acc[3][1], a23.y, bb.y);
        }
        __syncthreads();
    }

    float4 b4 = *(const float4*)(bias + f0 + tx * 4);
#pragma unroll
    for (int i = 0; i < 4; i++) {
        float o0, o1, o2, o3;
        unpk2(o0, o1, acc[i][0]);
        unpk2(o2, o3, acc[i][1]);
        float4 r = make_float4(o0 + b4.x, o1 + b4.y, o2 + b4.z, o3 + b4.w);
        *(float4*)(out + (m0 + ty * 4 + i) * E_DIM + f0 + tx * 4) = r;
    }
}

// ============================================================================
// Kernel 2: sliding-window attention.
// One CTA = 16 consecutive queries of one batch; key window = 144 keys
// [l0-64, l0+79]. Phase A: scores via e-chunked smem GEMM (acc in regs).
// Softmax in smem (probs stored k-major for broadcast LDS). Phase B: PV.
// ============================================================================
#define QB  16
#define KBW 144           // QB + 2*64
#define ECA 32            // e-chunk, score phase
#define ECB 64            // e-chunk, PV phase

__global__ void __launch_bounds__(256) local_attn(float* __restrict__ out)
{
    __shared__ float sKV[KBW][ECB];       // 36864 B (phase A uses cols 0..31)
    __shared__ float sQ[QB][ECA];         //  2048 B
    __shared__ float P[KBW][QB + 1];      //  9792 B   (k-major probs)

    const int t    = threadIdx.x;
    const int blk  = blockIdx.x;
    const int b    = blk >> 7;            // 128 query-blocks per batch
    const int l0   = (blk & 127) * QB;
    const int rowbase = b * L_SEQ + l0;
    const int kbase   = l0 - 64;          // global index of local key 0

    const int qi = t & 15;                // this thread's query
    const int kg = t >> 4;                // key sub-lane 0..15

    float acc[9];
#pragma unroll
    for (int i = 0; i < 9; i++) acc[i] = 0.f;

    // ---------------- Phase A: scores S[q][j] = q . k_j ----------------
    for (int ec = 0; ec < E_DIM; ec += ECA) {
        if (t < 128) {                    // load sQ 16x32
            int r = t >> 3, c4 = (t & 7) * 4;
            *(float4*)&sQ[r][c4] =
                *(const float4*)(g_q + (rowbase + r) * E_DIM + ec + c4);
        }
        for (int idx = t; idx < KBW * (ECA / 4); idx += 256) {  // sK 144x32
            int r = idx >> 3;
            int c4 = (idx & 7) * 4;
            int g = kbase + r;
            float4 v = (g >= 0 && g < L_SEQ)
                ? *(const float4*)(g_k + (b * L_SEQ + g) * E_DIM + ec + c4)
                : make_float4(0.f, 0.f, 0.f, 0.f);
            *(float4*)&sKV[r][c4] = v;
        }
        __syncthreads();

#pragma unroll
        for (int e = 0; e < ECA; e += 4) {
            float4 qv = *(const float4*)&sQ[qi][e];
#pragma unroll
            for (int i = 0; i < 9; i++) {
                int j = kg + 16 * i;
                float4 kv = *(const float4*)&sKV[j][e];
                acc[i] += qv.x * kv.x + qv.y * kv.y + qv.z * kv.z + qv.w * kv.w;
            }
        }
        __syncthreads();
    }

    // scale + mask -> P (k-major)
    const float scale = 0.044194173824159216f;   // 1/sqrt(512)
#pragma unroll
    for (int i = 0; i < 9; i++) {
        int j = kg + 16 * i;
        int g = kbase + j;
        bool valid = (g >= 0) && (g < L_SEQ) && (j >= qi) && (j <= qi + 128);
        P[j][qi] = valid ? acc[i] * scale : -3.0e38f;
    }
    __syncthreads();

    // ---------------- softmax: 8 warps x 2 queries ----------------
    {
        const int warp = t >> 5, lane = t & 31;
#pragma unroll
        for (int qq = 0; qq < 2; qq++) {
            int q = warp * 2 + qq;
            float v[5];
#pragma unroll
            for (int i = 0; i < 5; i++) {
                int k = lane + 32 * i;
                v[i] = (k < KBW) ? P[k][q] : -3.0e38f;
            }
            float mx = v[0];
#pragma unroll
            for (int i = 1; i < 5; i++) mx = fmaxf(mx, v[i]);
#pragma unroll
            for (int o = 16; o; o >>= 1) mx = fmaxf(mx, __shfl_xor_sync(0xffffffffu, mx, o));
            float s = 0.f;
#pragma unroll
            for (int i = 0; i < 5; i++) { v[i] = __expf(v[i] - mx); s += v[i]; }
#pragma unroll
            for (int o = 16; o; o >>= 1) s += __shfl_xor_sync(0xffffffffu, s, o);
            float inv = 1.0f / s;
#pragma unroll
            for (int i = 0; i < 5; i++) {
                int k = lane + 32 * i;
                if (k < KBW) P[k][q] = v[i] * inv;
            }
        }
    }
    __syncthreads();

    // ---------------- Phase B: out[q][e] = sum_j P[j][q] * v_j[e] ----------
    const int e4 = (t >> 4) * 4;          // 0..60
    for (int ec = 0; ec < E_DIM; ec += ECB) {
        for (int idx = t; idx < KBW * (ECB / 4); idx += 256) {  // sV 144x64
            int r = idx >> 4;
            int c4 = (idx & 15) * 4;
            int g = kbase + r;
            float4 v = (g >= 0 && g < L_SEQ)
                ? *(const float4*)(g_v + (b * L_SEQ + g) * E_DIM + ec + c4)
                : make_float4(0.f, 0.f, 0.f, 0.f);
            *(float4*)&sKV[r][c4] = v;
        }
        __syncthreads();

        float4 o = make_float4(0.f, 0.f, 0.f, 0.f);
#pragma unroll 4
        for (int j = 0; j < KBW; j++) {
            float p = P[j][qi];
            float4 vv = *(const float4*)&sKV[j][e4];
            o.x += p * vv.x; o.y += p * vv.y; o.z += p * vv.z; o.w += p * vv.w;
        }
        *(float4*)(out + (rowbase + qi) * E_DIM + ec + e4) = o;
        __syncthreads();
    }
}

// ============================================================================
// launch (graph-capturable: two kernel launches, no sync, no alloc)
// inputs: x, Wq, bq, Wk, bk, Wv, bv, window_size(=64, fixed)
// ============================================================================
extern "C" void kernel_launch(void* const* d_in, const int* in_sizes, int n_in,
                              void* d_out, int out_size)
{
    const float* x  = (const float*)d_in[0];
    const float* Wq = (const float*)d_in[1];
    const float* bq = (const float*)d_in[2];
    const float* Wk = (const float*)d_in[3];
    const float* bk = (const float*)d_in[4];
    const float* Wv = (const float*)d_in[5];
    const float* bv = (const float*)d_in[6];
    (void)in_sizes; (void)n_in; (void)out_size;

    dim3 g1(M_ROWS / BM, 24);             // (64, 24)
    qkv_gemm<<<g1, 256>>>(x, Wq, Wk, Wv, bq, bk, bv);

    local_attn<<<B_BATCH * (L_SEQ / QB), 256>>>((float*)d_out);
}

// round 9
// speedup vs baseline: 1.4052x; 1.4052x over previous
#include <cuda_runtime.h>
#include <cuda_bf16.h>

// Problem constants (fixed by setup_inputs): B=2, L=2048, E=512, window=64
#define L_SEQ   2048
#define E_DIM   512
#define B_BATCH 2
#define M_ROWS  (B_BATCH * L_SEQ)   // 4096

// ---------------- scratch (device globals; no allocation allowed) ----------
__device__ float g_q[M_ROWS * E_DIM];
__device__ float g_k[M_ROWS * E_DIM];
__device__ float g_v[M_ROWS * E_DIM];

typedef unsigned long long u64;

__device__ __forceinline__ u64 pk2(float lo, float hi) {
    u64 r;
    asm("mov.b64 %0, {%1,%2};" : "=l"(r) : "f"(lo), "f"(hi));
    return r;
}
__device__ __forceinline__ void fma2(u64 &d, u64 a, u64 b) {
    asm("fma.rn.f32x2 %0, %1, %2, %0;" : "+l"(d) : "l"(a), "l"(b));
}
__device__ __forceinline__ void unpk2(float &lo, float &hi, u64 v) {
    asm("mov.b64 {%0,%1}, %2;" : "=f"(lo), "=f"(hi) : "l"(v));
}

// ============================================================================
// Kernel 1: QKV projection.  out[m][f] = sum_e X[m][e] * W[f][e] + b[f]
// BM=128, BN=64, BK=16, 256 threads, 8x4 microtile.
// Accumulator pairs run along M: adjacent rows in As are contiguous floats,
// so A pairs are read directly as u64 (no dup needed); B scalars are dup'd
// with 4 MOVs/k (ALU pipe). Inner loop per k:
//   2x LDS.128 (A, 2-addr broadcast) + 1x LDS.128 (B) + 4 MOV + 16 FFMA2
// => FMA-pipe bound. Register-staged double buffer: 1 syncthreads per tile.
// ============================================================================
#define BM 128
#define BN 64
#define BK 16

__global__ void __launch_bounds__(256, 2) qkv_gemm(
    const float* __restrict__ X,
    const float* __restrict__ Wq, const float* __restrict__ Wk, const float* __restrict__ Wv,
    const float* __restrict__ bq, const float* __restrict__ bk, const float* __restrict__ bv)
{
    __shared__ float As[2][BK][BM];   // 16 KB
    __shared__ float Bs[2][BK][BN];   //  8 KB

    const int t  = threadIdx.x;
    const int m0 = blockIdx.x * BM;
    const int nb = blockIdx.y;           // 0..23
    const int mat = nb >> 3;             // 0=q, 1=k, 2=v
    const int f0  = (nb & 7) * BN;

    const float* W    = (mat == 0) ? Wq : (mat == 1) ? Wk : Wv;
    const float* bias = (mat == 0) ? bq : (mat == 1) ? bk : bv;
    float*       out  = (mat == 0) ? g_q : (mat == 1) ? g_k : g_v;

    // loader mapping
    const int ra = t >> 1;               // 0..127   A row
    const int ca = (t & 1) * 8;          // 0 or 8   A col base (8 cols)
    const int rb = t >> 2;               // 0..63    B row
    const int cb = (t & 3) * 4;          // 0..12    B col base (4 cols)

    const float* Ag = X + (m0 + ra) * E_DIM + ca;
    const float* Bg = W + (f0 + rb) * E_DIM + cb;

    // compute mapping
    const int tx = t & 15;               // 4 cols:  f0 + tx*4 ..
    const int ty = t >> 4;               // 8 rows:  m0 + ty*8 ..

    // prologue: load tile 0
    {
        float4 a0 = *(const float4*)(Ag);
        float4 a1 = *(const float4*)(Ag + 4);
        float4 b0 = *(const float4*)(Bg);
#pragma unroll
        for (int i = 0; i < 4; i++) {
            As[0][ca + i][ra]     = (&a0.x)[i];
            As[0][ca + 4 + i][ra] = (&a1.x)[i];
            Bs[0][cb + i][rb]     = (&b0.x)[i];
        }
    }
    __syncthreads();

    u64 acc[4][4];
#pragma unroll
    for (int p = 0; p < 4; p++)
#pragma unroll
        for (int c = 0; c < 4; c++) acc[p][c] = 0ull;

    int buf = 0;
    for (int kt = 0; kt < E_DIM; kt += BK) {
        float4 na0, na1, nb0;
        const bool more = (kt + BK) < E_DIM;
        if (more) {
            na0 = *(const float4*)(Ag + kt + BK);
            na1 = *(const float4*)(Ag + kt + BK + 4);
            nb0 = *(const float4*)(Bg + kt + BK);
        }

#pragma unroll
        for (int k = 0; k < BK; k++) {
            // A pairs: rows (ty*8 .. ty*8+7) as 4 u64 (adjacent-row pairs)
            ulonglong2 a01 = *(const ulonglong2*)&As[buf][k][ty * 8];
            ulonglong2 a23 = *(const ulonglong2*)&As[buf][k][ty * 8 + 4];
            float4 bv = *(const float4*)&Bs[buf][k][tx * 4];
            u64 bp0 = pk2(bv.x, bv.x);
            u64 bp1 = pk2(bv.y, bv.y);
            u64 bp2 = pk2(bv.z, bv.z);
            u64 bp3 = pk2(bv.w, bv.w);
            fma2(acc[0][0], a01.x, bp0); fma2(acc[0][1], a01.x, bp1);
            fma2(acc[0][2], a01.x, bp2); fma2(acc[0][3], a01.x, bp3);
            fma2(acc[1][0], a01.y, bp0); fma2(acc[1][1], a01.y, bp1);
            fma2(acc[1][2], a01.y, bp2); fma2(acc[1][3], a01.y, bp3);
            fma2(acc[2][0], a23.x, bp0); fma2(acc[2][1], a23.x, bp1);
            fma2(acc[2][2], a23.x, bp2); fma2(acc[2][3], a23.x, bp3);
            fma2(acc[3][0], a23.y, bp0); fma2(acc[3][1], a23.y, bp1);
            fma2(acc[3][2], a23.y, bp2); fma2(acc[3][3], a23.y, bp3);
        }

        if (more) {
            int nbuf = buf ^ 1;
#pragma unroll
            for (int i = 0; i < 4; i++) {
                As[nbuf][ca + i][ra]     = (&na0.x)[i];
                As[nbuf][ca + 4 + i][ra] = (&na1.x)[i];
                Bs[nbuf][cb + i][rb]     = (&nb0.x)[i];
            }
        }
        __syncthreads();
        buf ^= 1;
    }

    // epilogue: unpack pairs, add bias, store
    float4 b4 = *(const float4*)(bias + f0 + tx * 4);
#pragma unroll
    for (int p = 0; p < 4; p++) {
        float lo0, hi0, lo1, hi1, lo2, hi2, lo3, hi3;
        unpk2(lo0, hi0, acc[p][0]);
        unpk2(lo1, hi1, acc[p][1]);
        unpk2(lo2, hi2, acc[p][2]);
        unpk2(lo3, hi3, acc[p][3]);
        float4 r0 = make_float4(lo0 + b4.x, lo1 + b4.y, lo2 + b4.z, lo3 + b4.w);
        float4 r1 = make_float4(hi0 + b4.x, hi1 + b4.y, hi2 + b4.z, hi3 + b4.w);
        int row = m0 + ty * 8 + 2 * p;
        *(float4*)(out + (size_t)row * E_DIM + f0 + tx * 4)       = r0;
        *(float4*)(out + (size_t)(row + 1) * E_DIM + f0 + tx * 4) = r1;
    }
}

// ============================================================================
// Kernel 2: sliding-window attention.
// One CTA = 16 consecutive queries; key window = 144 keys [l0-64, l0+79].
// Phase A: scores with Q held TRANSPOSED in smem (sQt[e4][qi][4]) so the 16
// lanes with distinct qi read consecutive float4 -> conflict-free (was 16-way
// same-bank conflict). e-dim paired with FFMA2 (u64 accumulators).
// K/V smem reads are 2-address broadcasts (no conflict). P stays k-major
// (stride 17 -> conflict-free scalar reads in phase B).
// ============================================================================
#define QB  16
#define KBW 144           // QB + 2*64
#define ECA 32            // e-chunk, score phase
#define ECB 64            // e-chunk, PV phase

__global__ void __launch_bounds__(256) local_attn(float* __restrict__ out)
{
    __shared__ float sKV[KBW][ECB];       // 36864 B (phase A uses cols 0..31)
    __shared__ float sQt[8][QB][4];       //  2048 B (transposed Q chunk)
    __shared__ float P[KBW][QB + 1];      //  9792 B (k-major probs)

    const int t    = threadIdx.x;
    const int blk  = blockIdx.x;
    const int b    = blk >> 7;            // 128 query-blocks per batch
    const int l0   = (blk & 127) * QB;
    const int rowbase = b * L_SEQ + l0;
    const int kbase   = l0 - 64;          // global index of local key 0

    const int qi = t & 15;                // this thread's query
    const int kg = t >> 4;                // key sub-lane 0..15

    u64 acc2[9];
#pragma unroll
    for (int i = 0; i < 9; i++) acc2[i] = 0ull;

    // ---------------- Phase A: scores S[q][j] = q . k_j ----------------
    for (int ec = 0; ec < E_DIM; ec += ECA) {
        if (t < 128) {                    // load sQt: 16 q x 8 e4-chunks
            int r = t >> 3, c = t & 7;
            *(float4*)&sQt[c][r][0] =
                *(const float4*)(g_q + (size_t)(rowbase + r) * E_DIM + ec + c * 4);
        }
        for (int idx = t; idx < KBW * (ECA / 4); idx += 256) {  // sK 144x32
            int r = idx >> 3;
            int c4 = (idx & 7) * 4;
            int g = kbase + r;
            float4 v = (g >= 0 && g < L_SEQ)
                ? *(const float4*)(g_k + (size_t)(b * L_SEQ + g) * E_DIM + ec + c4)
                : make_float4(0.f, 0.f, 0.f, 0.f);
            *(float4*)&sKV[r][c4] = v;
        }
        __syncthreads();

#pragma unroll
        for (int e4 = 0; e4 < 8; e4++) {
            ulonglong2 qp = *(const ulonglong2*)&sQt[e4][qi][0];  // conflict-free
#pragma unroll
            for (int i = 0; i < 9; i++) {
                ulonglong2 kp = *(const ulonglong2*)&sKV[kg + 16 * i][e4 * 4];
                fma2(acc2[i], qp.x, kp.x);
                fma2(acc2[i], qp.y, kp.y);
            }
        }
        __syncthreads();
    }

    // scale + mask -> P (k-major)
    const float scale = 0.044194173824159216f;   // 1/sqrt(512)
#pragma unroll
    for (int i = 0; i < 9; i++) {
        int j = kg + 16 * i;
        int g = kbase + j;
        float lo, hi;
        unpk2(lo, hi, acc2[i]);
        float s = lo + hi;
        bool valid = (g >= 0) && (g < L_SEQ) && (j >= qi) && (j <= qi + 128);
        P[j][qi] = valid ? s * scale : -3.0e38f;
    }
    __syncthreads();

    // ---------------- softmax: 8 warps x 2 queries ----------------
    {
        const int warp = t >> 5, lane = t & 31;
#pragma unroll
        for (int qq = 0; qq < 2; qq++) {
            int q = warp * 2 + qq;
            float v[5];
#pragma unroll
            for (int i = 0; i < 5; i++) {
                int k = lane + 32 * i;
                v[i] = (k < KBW) ? P[k][q] : -3.0e38f;
            }
            float mx = v[0];
#pragma unroll
            for (int i = 1; i < 5; i++) mx = fmaxf(mx, v[i]);
#pragma unroll
            for (int o = 16; o; o >>= 1) mx = fmaxf(mx, __shfl_xor_sync(0xffffffffu, mx, o));
            float s = 0.f;
#pragma unroll
            for (int i = 0; i < 5; i++) { v[i] = __expf(v[i] - mx); s += v[i]; }
#pragma unroll
            for (int o = 16; o; o >>= 1) s += __shfl_xor_sync(0xffffffffu, s, o);
            float inv = 1.0f / s;
#pragma unroll
            for (int i = 0; i < 5; i++) {
                int k = lane + 32 * i;
                if (k < KBW) P[k][q] = v[i] * inv;
            }
        }
    }
    __syncthreads();

    // ---------------- Phase B: out[q][e] = sum_j P[j][q] * v_j[e] ----------
    const int e4 = (t >> 4) * 4;          // 0..60
    for (int ec = 0; ec < E_DIM; ec += ECB) {
        for (int idx = t; idx < KBW * (ECB / 4); idx += 256) {  // sV 144x64
            int r = idx >> 4;
            int c4 = (idx & 15) * 4;
            int g = kbase + r;
            float4 v = (g >= 0 && g < L_SEQ)
                ? *(const float4*)(g_v + (size_t)(b * L_SEQ + g) * E_DIM + ec + c4)
                : make_float4(0.f, 0.f, 0.f, 0.f);
            *(float4*)&sKV[r][c4] = v;
        }
        __syncthreads();

        float4 o = make_float4(0.f, 0.f, 0.f, 0.f);
#pragma unroll 8
        for (int j = 0; j < KBW; j++) {
            float p = P[j][qi];                          // conflict-free (stride 17)
            float4 vv = *(const float4*)&sKV[j][e4];     // 2-addr broadcast
            o.x += p * vv.x; o.y += p * vv.y; o.z += p * vv.z; o.w += p * vv.w;
        }
        *(float4*)(out + (size_t)(rowbase + qi) * E_DIM + ec + e4) = o;
        __syncthreads();
    }
}

// ============================================================================
// launch (graph-capturable: two kernel launches, no sync, no alloc)
// inputs: x, Wq, bq, Wk, bk, Wv, bv, window_size(=64, fixed)
// ============================================================================
extern "C" void kernel_launch(void* const* d_in, const int* in_sizes, int n_in,
                              void* d_out, int out_size)
{
    const float* x  = (const float*)d_in[0];
    const float* Wq = (const float*)d_in[1];
    const float* bq = (const float*)d_in[2];
    const float* Wk = (const float*)d_in[3];
    const float* bk = (const float*)d_in[4];
    const float* Wv = (const float*)d_in[5];
    const float* bv = (const float*)d_in[6];
    (void)in_sizes; (void)n_in; (void)out_size;

    dim3 g1(M_ROWS / BM, 24);             // (32, 24) = 768 CTAs
    qkv_gemm<<<g1, 256>>>(x, Wq, Wk, Wv, bq, bk, bv);

    local_attn<<<B_BATCH * (L_SEQ / QB), 256>>>((float*)d_out);
}

// round 10
// speedup vs baseline: 1.9739x; 1.4047x over previous
#include <cuda_runtime.h>
#include <cuda_bf16.h>
#include <cstdint>

// Problem constants (fixed by setup_inputs): B=2, L=2048, E=512, window=64
#define L_SEQ   2048
#define E_DIM   512
#define B_BATCH 2
#define M_ROWS  (B_BATCH * L_SEQ)   // 4096

// ---------------- scratch (device globals; no allocation allowed) ----------
__device__ float g_q[M_ROWS * E_DIM];
__device__ float g_k[M_ROWS * E_DIM];
__device__ float g_v[M_ROWS * E_DIM];

typedef unsigned long long u64;

__device__ __forceinline__ u64 pk2(float lo, float hi) {
    u64 r;
    asm("mov.b64 %0, {%1,%2};" : "=l"(r) : "f"(lo), "f"(hi));
    return r;
}
__device__ __forceinline__ void fma2(u64 &d, u64 a, u64 b) {
    asm("fma.rn.f32x2 %0, %1, %2, %0;" : "+l"(d) : "l"(a), "l"(b));
}
__device__ __forceinline__ void unpk2(float &lo, float &hi, u64 v) {
    asm("mov.b64 {%0,%1}, %2;" : "=f"(lo), "=f"(hi) : "l"(v));
}

// ============================================================================
// Kernel 1: QKV projection on TENSOR CORES (tf32 mma.sync.m16n8k8).
//   out[m][f] = sum_e X[m][e] * W[f][e] + b[f]
// BM=128, BN=64, BK=16, 256 threads (8 warps, 4x2 warp grid, 32x32 warp tile).
// Operands held in smem as tf32 bits, m-major/n-major with row stride 20:
//   fragment-load bank = (20*lr + kq) % 32 -> all 32 banks distinct
//   => ZERO conflicts in the hot loop (16 LDS.32 + 8 HMMA per k-step of 8).
// fp32 -> tf32 via cvt.rna at smem-fill time (once per element).
// Double-buffered tiles, register-staged prefetch, 1 syncthreads per tile.
// ============================================================================
#define BM 128
#define BN 64
#define BK 16
#define KSTR (BK + 4)   // 20 -> conflict-free fragment loads

__device__ __forceinline__ uint32_t cvt_tf32(float f) {
    uint32_t u;
    asm("cvt.rna.tf32.f32 %0, %1;" : "=r"(u) : "f"(f));
    return u;
}

__device__ __forceinline__ void mma_tf32(float c[4], const uint32_t a[4], const uint32_t b[2]) {
    asm volatile(
        "mma.sync.aligned.m16n8k8.row.col.f32.tf32.tf32.f32 "
        "{%0,%1,%2,%3}, {%4,%5,%6,%7}, {%8,%9}, {%0,%1,%2,%3};"
        : "+f"(c[0]), "+f"(c[1]), "+f"(c[2]), "+f"(c[3])
        : "r"(a[0]), "r"(a[1]), "r"(a[2]), "r"(a[3]), "r"(b[0]), "r"(b[1]));
}

__global__ void __launch_bounds__(256, 2) qkv_gemm(
    const float* __restrict__ X,
    const float* __restrict__ Wq, const float* __restrict__ Wk, const float* __restrict__ Wv,
    const float* __restrict__ bq, const float* __restrict__ bk, const float* __restrict__ bv)
{
    __shared__ uint32_t As[2][BM][KSTR];   // 20480 B
    __shared__ uint32_t Bs[2][BN][KSTR];   // 10240 B

    const int t    = threadIdx.x;
    const int warp = t >> 5, lane = t & 31;
    const int wm   = warp & 3;             // 4 warps along M (32 rows each)
    const int wn   = warp >> 2;            // 2 warps along N (32 cols each)
    const int kq   = lane & 3;             // thread-in-group (k / col-pair idx)
    const int lr   = lane >> 2;            // group id (row idx)

    const int m0  = blockIdx.x * BM;
    const int nb  = blockIdx.y;            // 0..23
    const int mat = nb >> 3;               // 0=q, 1=k, 2=v
    const int f0  = (nb & 7) * BN;

    const float* W    = (mat == 0) ? Wq : (mat == 1) ? Wk : Wv;
    const float* bias = (mat == 0) ? bq : (mat == 1) ? bk : bv;
    float*       out  = (mat == 0) ? g_q : (mat == 1) ? g_k : g_v;

    // loader mapping
    const int ra = t >> 1;                 // 0..127  A row (m)
    const int ca = (t & 1) * 8;            // 0 or 8  A k-col base (8 cols)
    const int rb = t >> 2;                 // 0..63   B row (n)
    const int cb = (t & 3) * 4;            // 0..12   B k-col base (4 cols)

    const float* Ag = X + (size_t)(m0 + ra) * E_DIM + ca;
    const float* Bg = W + (size_t)(f0 + rb) * E_DIM + cb;

    // prologue: tile 0
    {
        float4 a0 = *(const float4*)(Ag);
        float4 a1 = *(const float4*)(Ag + 4);
        float4 b0 = *(const float4*)(Bg);
        uint4 ua0 = make_uint4(cvt_tf32(a0.x), cvt_tf32(a0.y), cvt_tf32(a0.z), cvt_tf32(a0.w));
        uint4 ua1 = make_uint4(cvt_tf32(a1.x), cvt_tf32(a1.y), cvt_tf32(a1.z), cvt_tf32(a1.w));
        uint4 ub0 = make_uint4(cvt_tf32(b0.x), cvt_tf32(b0.y), cvt_tf32(b0.z), cvt_tf32(b0.w));
        *(uint4*)&As[0][ra][ca]     = ua0;
        *(uint4*)&As[0][ra][ca + 4] = ua1;
        *(uint4*)&Bs[0][rb][cb]     = ub0;
    }
    __syncthreads();

    float acc[2][4][4];
#pragma unroll
    for (int mt = 0; mt < 2; mt++)
#pragma unroll
        for (int nt = 0; nt < 4; nt++)
#pragma unroll
            for (int i = 0; i < 4; i++) acc[mt][nt][i] = 0.f;

    int buf = 0;
    for (int kt = 0; kt < E_DIM; kt += BK) {
        float4 na0, na1, nb0;
        const bool more = (kt + BK) < E_DIM;
        if (more) {
            na0 = *(const float4*)(Ag + kt + BK);
            na1 = *(const float4*)(Ag + kt + BK + 4);
            nb0 = *(const float4*)(Bg + kt + BK);
        }

#pragma unroll
        for (int ks = 0; ks < BK; ks += 8) {
            uint32_t af[2][4], bf[4][2];
#pragma unroll
            for (int mt = 0; mt < 2; mt++) {
                int m = wm * 32 + mt * 16 + lr;
                af[mt][0] = As[buf][m][ks + kq];        // a0: (row, k)
                af[mt][1] = As[buf][m + 8][ks + kq];    // a1: (row+8, k)
                af[mt][2] = As[buf][m][ks + kq + 4];    // a2: (row, k+4)
                af[mt][3] = As[buf][m + 8][ks + kq + 4];// a3: (row+8, k+4)
            }
#pragma unroll
            for (int nt = 0; nt < 4; nt++) {
                int n = wn * 32 + nt * 8 + lr;
                bf[nt][0] = Bs[buf][n][ks + kq];        // b0: (k, col)
                bf[nt][1] = Bs[buf][n][ks + kq + 4];    // b1: (k+4, col)
            }
#pragma unroll
            for (int mt = 0; mt < 2; mt++)
#pragma unroll
                for (int nt = 0; nt < 4; nt++)
                    mma_tf32(acc[mt][nt], af[mt], bf[nt]);
        }

        if (more) {
            int nbuf = buf ^ 1;
            uint4 ua0 = make_uint4(cvt_tf32(na0.x), cvt_tf32(na0.y), cvt_tf32(na0.z), cvt_tf32(na0.w));
            uint4 ua1 = make_uint4(cvt_tf32(na1.x), cvt_tf32(na1.y), cvt_tf32(na1.z), cvt_tf32(na1.w));
            uint4 ub0 = make_uint4(cvt_tf32(nb0.x), cvt_tf32(nb0.y), cvt_tf32(nb0.z), cvt_tf32(nb0.w));
            *(uint4*)&As[nbuf][ra][ca]     = ua0;
            *(uint4*)&As[nbuf][ra][ca + 4] = ua1;
            *(uint4*)&Bs[nbuf][rb][cb]     = ub0;
        }
        __syncthreads();
        buf ^= 1;
    }

    // epilogue: bias + store (c0,c1 = cols 2kq,2kq+1 @ row; c2,c3 @ row+8)
#pragma unroll
    for (int mt = 0; mt < 2; mt++) {
#pragma unroll
        for (int nt = 0; nt < 4; nt++) {
            int row = m0 + wm * 32 + mt * 16 + lr;
            int col = f0 + wn * 32 + nt * 8 + 2 * kq;
            float2 bb = *(const float2*)(bias + col);
            *(float2*)(out + (size_t)row * E_DIM + col) =
                make_float2(acc[mt][nt][0] + bb.x, acc[mt][nt][1] + bb.y);
            *(float2*)(out + (size_t)(row + 8) * E_DIM + col) =
                make_float2(acc[mt][nt][2] + bb.x, acc[mt][nt][3] + bb.y);
        }
    }
}

// ============================================================================
// Kernel 2: sliding-window attention (UNCHANGED from R9 for clean attribution).
// ============================================================================
#define QB  16
#define KBW 144           // QB + 2*64
#define ECA 32            // e-chunk, score phase
#define ECB 64            // e-chunk, PV phase

__global__ void __launch_bounds__(256) local_attn(float* __restrict__ out)
{
    __shared__ float sKV[KBW][ECB];       // 36864 B (phase A uses cols 0..31)
    __shared__ float sQt[8][QB][4];       //  2048 B (transposed Q chunk)
    __shared__ float P[KBW][QB + 1];      //  9792 B (k-major probs)

    const int t    = threadIdx.x;
    const int blk  = blockIdx.x;
    const int b    = blk >> 7;            // 128 query-blocks per batch
    const int l0   = (blk & 127) * QB;
    const int rowbase = b * L_SEQ + l0;
    const int kbase   = l0 - 64;          // global index of local key 0

    const int qi = t & 15;                // this thread's query
    const int kg = t >> 4;                // key sub-lane 0..15

    u64 acc2[9];
#pragma unroll
    for (int i = 0; i < 9; i++) acc2[i] = 0ull;

    // ---------------- Phase A: scores S[q][j] = q . k_j ----------------
    for (int ec = 0; ec < E_DIM; ec += ECA) {
        if (t < 128) {                    // load sQt: 16 q x 8 e4-chunks
            int r = t >> 3, c = t & 7;
            *(float4*)&sQt[c][r][0] =
                *(const float4*)(g_q + (size_t)(rowbase + r) * E_DIM + ec + c * 4);
        }
        for (int idx = t; idx < KBW * (ECA / 4); idx += 256) {  // sK 144x32
            int r = idx >> 3;
            int c4 = (idx & 7) * 4;
            int g = kbase + r;
            float4 v = (g >= 0 && g < L_SEQ)
                ? *(const float4*)(g_k + (size_t)(b * L_SEQ + g) * E_DIM + ec + c4)
                : make_float4(0.f, 0.f, 0.f, 0.f);
            *(float4*)&sKV[r][c4] = v;
        }
        __syncthreads();

#pragma unroll
        for (int e4 = 0; e4 < 8; e4++) {
            ulonglong2 qp = *(const ulonglong2*)&sQt[e4][qi][0];  // conflict-free
#pragma unroll
            for (int i = 0; i < 9; i++) {
                ulonglong2 kp = *(const ulonglong2*)&sKV[kg + 16 * i][e4 * 4];
                fma2(acc2[i], qp.x, kp.x);
                fma2(acc2[i], qp.y, kp.y);
            }
        }
        __syncthreads();
    }

    // scale + mask -> P (k-major)
    const float scale = 0.044194173824159216f;   // 1/sqrt(512)
#pragma unroll
    for (int i = 0; i < 9; i++) {
        int j = kg + 16 * i;
        int g = kbase + j;
        float lo, hi;
        unpk2(lo, hi, acc2[i]);
        float s = lo + hi;
        bool valid = (g >= 0) && (g < L_SEQ) && (j >= qi) && (j <= qi + 128);
        P[j][qi] = valid ? s * scale : -3.0e38f;
    }
    __syncthreads();

    // ---------------- softmax: 8 warps x 2 queries ----------------
    {
        const int warp = t >> 5, lane = t & 31;
#pragma unroll
        for (int qq = 0; qq < 2; qq++) {
            int q = warp * 2 + qq;
            float v[5];
#pragma unroll
            for (int i = 0; i < 5; i++) {
                int k = lane + 32 * i;
                v[i] = (k < KBW) ? P[k][q] : -3.0e38f;
            }
            float mx = v[0];
#pragma unroll
            for (int i = 1; i < 5; i++) mx = fmaxf(mx, v[i]);
#pragma unroll
            for (int o = 16; o; o >>= 1) mx = fmaxf(mx, __shfl_xor_sync(0xffffffffu, mx, o));
            float s = 0.f;
#pragma unroll
            for (int i = 0; i < 5; i++) { v[i] = __expf(v[i] - mx); s += v[i]; }
#pragma unroll
            for (int o = 16; o; o >>= 1) s += __shfl_xor_sync(0xffffffffu, s, o);
            float inv = 1.0f / s;
#pragma unroll
            for (int i = 0; i < 5; i++) {
                int k = lane + 32 * i;
                if (k < KBW) P[k][q] = v[i] * inv;
            }
        }
    }
    __syncthreads();

    // ---------------- Phase B: out[q][e] = sum_j P[j][q] * v_j[e] ----------
    const int e4 = (t >> 4) * 4;          // 0..60
    for (int ec = 0; ec < E_DIM; ec += ECB) {
        for (int idx = t; idx < KBW * (ECB / 4); idx += 256) {  // sV 144x64
            int r = idx >> 4;
            int c4 = (idx & 15) * 4;
            int g = kbase + r;
            float4 v = (g >= 0 && g < L_SEQ)
                ? *(const float4*)(g_v + (size_t)(b * L_SEQ + g) * E_DIM + ec + c4)
                : make_float4(0.f, 0.f, 0.f, 0.f);
            *(float4*)&sKV[r][c4] = v;
        }
        __syncthreads();

        float4 o = make_float4(0.f, 0.f, 0.f, 0.f);
#pragma unroll 8
        for (int j = 0; j < KBW; j++) {
            float p = P[j][qi];                          // conflict-free (stride 17)
            float4 vv = *(const float4*)&sKV[j][e4];     // 2-addr broadcast
            o.x += p * vv.x; o.y += p * vv.y; o.z += p * vv.z; o.w += p * vv.w;
        }
        *(float4*)(out + (size_t)(rowbase + qi) * E_DIM + ec + e4) = o;
        __syncthreads();
    }
}

// ============================================================================
// launch (graph-capturable: two kernel launches, no sync, no alloc)
// inputs: x, Wq, bq, Wk, bk, Wv, bv, window_size(=64, fixed)
// ============================================================================
extern "C" void kernel_launch(void* const* d_in, const int* in_sizes, int n_in,
                              void* d_out, int out_size)
{
    const float* x  = (const float*)d_in[0];
    const float* Wq = (const float*)d_in[1];
    const float* bq = (const float*)d_in[2];
    const float* Wk = (const float*)d_in[3];
    const float* bk = (const float*)d_in[4];
    const float* Wv = (const float*)d_in[5];
    const float* bv = (const float*)d_in[6];
    (void)in_sizes; (void)n_in; (void)out_size;

    dim3 g1(M_ROWS / BM, 24);             // (32, 24) = 768 CTAs
    qkv_gemm<<<g1, 256>>>(x, Wq, Wk, Wv, bq, bk, bv);

    local_attn<<<B_BATCH * (L_SEQ / QB), 256>>>((float*)d_out);
}

// round 11
// speedup vs baseline: 1.9864x; 1.0063x over previous
#include <cuda_runtime.h>
#include <cuda_bf16.h>
#include <cstdint>

// Problem constants (fixed by setup_inputs): B=2, L=2048, E=512, window=64
#define L_SEQ   2048
#define E_DIM   512
#define B_BATCH 2
#define M_ROWS  (B_BATCH * L_SEQ)   // 4096

// ---------------- scratch (device globals; no allocation allowed) ----------
__device__ float g_q[M_ROWS * E_DIM];
__device__ float g_k[M_ROWS * E_DIM];
__device__ float g_v[M_ROWS * E_DIM];

typedef unsigned long long u64;

__device__ __forceinline__ u64 pk2(float lo, float hi) {
    u64 r;
    asm("mov.b64 %0, {%1,%2};" : "=l"(r) : "f"(lo), "f"(hi));
    return r;
}
__device__ __forceinline__ void fma2(u64 &d, u64 a, u64 b) {
    asm("fma.rn.f32x2 %0, %1, %2, %0;" : "+l"(d) : "l"(a), "l"(b));
}
__device__ __forceinline__ void unpk2(float &lo, float &hi, u64 v) {
    asm("mov.b64 {%0,%1}, %2;" : "=f"(lo), "=f"(hi) : "l"(v));
}

// ============================================================================
// Kernel 1: QKV projection on TENSOR CORES (tf32 mma.sync.m16n8k8).
//   out[m][f] = sum_e X[m][e] * W[f][e] + b[f]
// BM=128, BN=64, BK=16, 256 threads (8 warps, 4x2 warp grid, 32x32 warp tile).
// Operands held in smem as tf32 bits, m-major/n-major with row stride 20:
//   fragment-load bank = (20*lr + kq) % 32 -> all 32 banks distinct
//   => ZERO conflicts in the hot loop (16 LDS.32 + 8 HMMA per k-step of 8).
// fp32 -> tf32 via cvt.rna at smem-fill time (once per element).
// Double-buffered tiles, register-staged prefetch, 1 syncthreads per tile.
// ============================================================================
#define BM 128
#define BN 64
#define BK 16
#define KSTR (BK + 4)   // 20 -> conflict-free fragment loads

__device__ __forceinline__ uint32_t cvt_tf32(float f) {
    uint32_t u;
    asm("cvt.rna.tf32.f32 %0, %1;" : "=r"(u) : "f"(f));
    return u;
}

__device__ __forceinline__ void mma_tf32(float c[4], const uint32_t a[4], const uint32_t b[2]) {
    asm volatile(
        "mma.sync.aligned.m16n8k8.row.col.f32.tf32.tf32.f32 "
        "{%0,%1,%2,%3}, {%4,%5,%6,%7}, {%8,%9}, {%0,%1,%2,%3};"
        : "+f"(c[0]), "+f"(c[1]), "+f"(c[2]), "+f"(c[3])
        : "r"(a[0]), "r"(a[1]), "r"(a[2]), "r"(a[3]), "r"(b[0]), "r"(b[1]));
}

__global__ void __launch_bounds__(256, 2) qkv_gemm(
    const float* __restrict__ X,
    const float* __restrict__ Wq, const float* __restrict__ Wk, const float* __restrict__ Wv,
    const float* __restrict__ bq, const float* __restrict__ bk, const float* __restrict__ bv)
{
    __shared__ uint32_t As[2][BM][KSTR];   // 20480 B
    __shared__ uint32_t Bs[2][BN][KSTR];   // 10240 B

    const int t    = threadIdx.x;
    const int warp = t >> 5, lane = t & 31;
    const int wm   = warp & 3;             // 4 warps along M (32 rows each)
    const int wn   = warp >> 2;            // 2 warps along N (32 cols each)
    const int kq   = lane & 3;             // thread-in-group (k / col-pair idx)
    const int lr   = lane >> 2;            // group id (row idx)

    const int m0  = blockIdx.x * BM;
    const int nb  = blockIdx.y;            // 0..23
    const int mat = nb >> 3;               // 0=q, 1=k, 2=v
    const int f0  = (nb & 7) * BN;

    const float* W    = (mat == 0) ? Wq : (mat == 1) ? Wk : Wv;
    const float* bias = (mat == 0) ? bq : (mat == 1) ? bk : bv;
    float*       out  = (mat == 0) ? g_q : (mat == 1) ? g_k : g_v;

    // loader mapping
    const int ra = t >> 1;                 // 0..127  A row (m)
    const int ca = (t & 1) * 8;            // 0 or 8  A k-col base (8 cols)
    const int rb = t >> 2;                 // 0..63   B row (n)
    const int cb = (t & 3) * 4;            // 0..12   B k-col base (4 cols)

    const float* Ag = X + (size_t)(m0 + ra) * E_DIM + ca;
    const float* Bg = W + (size_t)(f0 + rb) * E_DIM + cb;

    // prologue: tile 0
    {
        float4 a0 = *(const float4*)(Ag);
        float4 a1 = *(const float4*)(Ag + 4);
        float4 b0 = *(const float4*)(Bg);
        uint4 ua0 = make_uint4(cvt_tf32(a0.x), cvt_tf32(a0.y), cvt_tf32(a0.z), cvt_tf32(a0.w));
        uint4 ua1 = make_uint4(cvt_tf32(a1.x), cvt_tf32(a1.y), cvt_tf32(a1.z), cvt_tf32(a1.w));
        uint4 ub0 = make_uint4(cvt_tf32(b0.x), cvt_tf32(b0.y), cvt_tf32(b0.z), cvt_tf32(b0.w));
        *(uint4*)&As[0][ra][ca]     = ua0;
        *(uint4*)&As[0][ra][ca + 4] = ua1;
        *(uint4*)&Bs[0][rb][cb]     = ub0;
    }
    __syncthreads();

    float acc[2][4][4];
#pragma unroll
    for (int mt = 0; mt < 2; mt++)
#pragma unroll
        for (int nt = 0; nt < 4; nt++)
#pragma unroll
            for (int i = 0; i < 4; i++) acc[mt][nt][i] = 0.f;

    int buf = 0;
    for (int kt = 0; kt < E_DIM; kt += BK) {
        float4 na0, na1, nb0;
        const bool more = (kt + BK) < E_DIM;
        if (more) {
            na0 = *(const float4*)(Ag + kt + BK);
            na1 = *(const float4*)(Ag + kt + BK + 4);
            nb0 = *(const float4*)(Bg + kt + BK);
        }

#pragma unroll
        for (int ks = 0; ks < BK; ks += 8) {
            uint32_t af[2][4], bf[4][2];
#pragma unroll
            for (int mt = 0; mt < 2; mt++) {
                int m = wm * 32 + mt * 16 + lr;
                af[mt][0] = As[buf][m][ks + kq];        // a0: (row, k)
                af[mt][1] = As[buf][m + 8][ks + kq];    // a1: (row+8, k)
                af[mt][2] = As[buf][m][ks + kq + 4];    // a2: (row, k+4)
                af[mt][3] = As[buf][m + 8][ks + kq + 4];// a3: (row+8, k+4)
            }
#pragma unroll
            for (int nt = 0; nt < 4; nt++) {
                int n = wn * 32 + nt * 8 + lr;
                bf[nt][0] = Bs[buf][n][ks + kq];        // b0: (k, col)
                bf[nt][1] = Bs[buf][n][ks + kq + 4];    // b1: (k+4, col)
            }
#pragma unroll
            for (int mt = 0; mt < 2; mt++)
#pragma unroll
                for (int nt = 0; nt < 4; nt++)
                    mma_tf32(acc[mt][nt], af[mt], bf[nt]);
        }

        if (more) {
            int nbuf = buf ^ 1;
            uint4 ua0 = make_uint4(cvt_tf32(na0.x), cvt_tf32(na0.y), cvt_tf32(na0.z), cvt_tf32(na0.w));
            uint4 ua1 = make_uint4(cvt_tf32(na1.x), cvt_tf32(na1.y), cvt_tf32(na1.z), cvt_tf32(na1.w));
            uint4 ub0 = make_uint4(cvt_tf32(nb0.x), cvt_tf32(nb0.y), cvt_tf32(nb0.z), cvt_tf32(nb0.w));
            *(uint4*)&As[nbuf][ra][ca]     = ua0;
            *(uint4*)&As[nbuf][ra][ca + 4] = ua1;
            *(uint4*)&Bs[nbuf][rb][cb]     = ub0;
        }
        __syncthreads();
        buf ^= 1;
    }

    // epilogue: bias + store (c0,c1 = cols 2kq,2kq+1 @ row; c2,c3 @ row+8)
#pragma unroll
    for (int mt = 0; mt < 2; mt++) {
#pragma unroll
        for (int nt = 0; nt < 4; nt++) {
            int row = m0 + wm * 32 + mt * 16 + lr;
            int col = f0 + wn * 32 + nt * 8 + 2 * kq;
            float2 bb = *(const float2*)(bias + col);
            *(float2*)(out + (size_t)row * E_DIM + col) =
                make_float2(acc[mt][nt][0] + bb.x, acc[mt][nt][1] + bb.y);
            *(float2*)(out + (size_t)(row + 8) * E_DIM + col) =
                make_float2(acc[mt][nt][2] + bb.x, acc[mt][nt][3] + bb.y);
        }
    }
}

// ============================================================================
// Kernel 2: sliding-window attention (UNCHANGED from R9 for clean attribution).
// ============================================================================
#define QB  16
#define KBW 144           // QB + 2*64
#define ECA 32            // e-chunk, score phase
#define ECB 64            // e-chunk, PV phase

__global__ void __launch_bounds__(256) local_attn(float* __restrict__ out)
{
    __shared__ float sKV[KBW][ECB];       // 36864 B (phase A uses cols 0..31)
    __shared__ float sQt[8][QB][4];       //  2048 B (transposed Q chunk)
    __shared__ float P[KBW][QB + 1];      //  9792 B (k-major probs)

    const int t    = threadIdx.x;
    const int blk  = blockIdx.x;
    const int b    = blk >> 7;            // 128 query-blocks per batch
    const int l0   = (blk & 127) * QB;
    const int rowbase = b * L_SEQ + l0;
    const int kbase   = l0 - 64;          // global index of local key 0

    const int qi = t & 15;                // this thread's query
    const int kg = t >> 4;                // key sub-lane 0..15

    u64 acc2[9];
#pragma unroll
    for (int i = 0; i < 9; i++) acc2[i] = 0ull;

    // ---------------- Phase A: scores S[q][j] = q . k_j ----------------
    for (int ec = 0; ec < E_DIM; ec += ECA) {
        if (t < 128) {                    // load sQt: 16 q x 8 e4-chunks
            int r = t >> 3, c = t & 7;
            *(float4*)&sQt[c][r][0] =
                *(const float4*)(g_q + (size_t)(rowbase + r) * E_DIM + ec + c * 4);
        }
        for (int idx = t; idx < KBW * (ECA / 4); idx += 256) {  // sK 144x32
            int r = idx >> 3;
            int c4 = (idx & 7) * 4;
            int g = kbase + r;
            float4 v = (g >= 0 && g < L_SEQ)
                ? *(const float4*)(g_k + (size_t)(b * L_SEQ + g) * E_DIM + ec + c4)
                : make_float4(0.f, 0.f, 0.f, 0.f);
            *(float4*)&sKV[r][c4] = v;
        }
        __syncthreads();

#pragma unroll
        for (int e4 = 0; e4 < 8; e4++) {
            ulonglong2 qp = *(const ulonglong2*)&sQt[e4][qi][0];  // conflict-free
#pragma unroll
            for (int i = 0; i < 9; i++) {
                ulonglong2 kp = *(const ulonglong2*)&sKV[kg + 16 * i][e4 * 4];
                fma2(acc2[i], qp.x, kp.x);
                fma2(acc2[i], qp.y, kp.y);
            }
        }
        __syncthreads();
    }

    // scale + mask -> P (k-major)
    const float scale = 0.044194173824159216f;   // 1/sqrt(512)
#pragma unroll
    for (int i = 0; i < 9; i++) {
        int j = kg + 16 * i;
        int g = kbase + j;
        float lo, hi;
        unpk2(lo, hi, acc2[i]);
        float s = lo + hi;
        bool valid = (g >= 0) && (g < L_SEQ) && (j >= qi) && (j <= qi + 128);
        P[j][qi] = valid ? s * scale : -3.0e38f;
    }
    __syncthreads();

    // ---------------- softmax: 8 warps x 2 queries ----------------
    {
        const int warp = t >> 5, lane = t & 31;
#pragma unroll
        for (int qq = 0; qq < 2; qq++) {
            int q = warp * 2 + qq;
            float v[5];
#pragma unroll
            for (int i = 0; i < 5; i++) {
                int k = lane + 32 * i;
                v[i] = (k < KBW) ? P[k][q] : -3.0e38f;
            }
            float mx = v[0];
#pragma unroll
            for (int i = 1; i < 5; i++) mx = fmaxf(mx, v[i]);
#pragma unroll
            for (int o = 16; o; o >>= 1) mx = fmaxf(mx, __shfl_xor_sync(0xffffffffu, mx, o));
            float s = 0.f;
#pragma unroll
            for (int i = 0; i < 5; i++) { v[i] = __expf(v[i] - mx); s += v[i]; }
#pragma unroll
            for (int o = 16; o; o >>= 1) s += __shfl_xor_sync(0xffffffffu, s, o);
            float inv = 1.0f / s;
#pragma unroll
            for (int i = 0; i < 5; i++) {
                int k = lane + 32 * i;
                if (k < KBW) P[k][q] = v[i] * inv;
            }
        }
    }
    __syncthreads();

    // ---------------- Phase B: out[q][e] = sum_j P[j][q] * v_j[e] ----------
    const int e4 = (t >> 4) * 4;          // 0..60
    for (int ec = 0; ec < E_DIM; ec += ECB) {
        for (int idx = t; idx < KBW * (ECB / 4); idx += 256) {  // sV 144x64
            int r = idx >> 4;
            int c4 = (idx & 15) * 4;
            int g = kbase + r;
            float4 v = (g >= 0 && g < L_SEQ)
                ? *(const float4*)(g_v + (size_t)(b * L_SEQ + g) * E_DIM + ec + c4)
                : make_float4(0.f, 0.f, 0.f, 0.f);
            *(float4*)&sKV[r][c4] = v;
        }
        __syncthreads();

        float4 o = make_float4(0.f, 0.f, 0.f, 0.f);
#pragma unroll 8
        for (int j = 0; j < KBW; j++) {
            float p = P[j][qi];                          // conflict-free (stride 17)
            float4 vv = *(const float4*)&sKV[j][e4];     // 2-addr broadcast
            o.x += p * vv.x; o.y += p * vv.y; o.z += p * vv.z; o.w += p * vv.w;
        }
        *(float4*)(out + (size_t)(rowbase + qi) * E_DIM + ec + e4) = o;
        __syncthreads();
    }
}

// ============================================================================
// launch (graph-capturable: two kernel launches, no sync, no alloc)
// inputs: x, Wq, bq, Wk, bk, Wv, bv, window_size(=64, fixed)
// ============================================================================
extern "C" void kernel_launch(void* const* d_in, const int* in_sizes, int n_in,
                              void* d_out, int out_size)
{
    const float* x  = (const float*)d_in[0];
    const float* Wq = (const float*)d_in[1];
    const float* bq = (const float*)d_in[2];
    const float* Wk = (const float*)d_in[3];
    const float* bk = (const float*)d_in[4];
    const float* Wv = (const float*)d_in[5];
    const float* bv = (const float*)d_in[6];
    (void)in_sizes; (void)n_in; (void)out_size;

    dim3 g1(M_ROWS / BM, 24);             // (32, 24) = 768 CTAs
    qkv_gemm<<<g1, 256>>>(x, Wq, Wk, Wv, bq, bk, bv);

    local_attn<<<B_BATCH * (L_SEQ / QB), 256>>>((float*)d_out);
}